// round 3
// baseline (speedup 1.0000x reference)
#include <cuda_runtime.h>
#include <cstdint>

// Problem constants
#define BB 32
#define LL 128
#define FF 128
#define RR 4096
#define NITEMS 262144
#define CAP 32                       // bucket capacity (Poisson(2) tail -> overflow prob ~1e-20)
#define NPAIRS (BB * (RR / 2))       // 65536 row-pairs

// Scratch (device globals; no allocation allowed)
__device__ int g_count[BB * RR];           // 512 KB
__device__ int g_bucket[BB * RR * CAP];    // 16 MB, entries = (slot<<18)|item

// ---------------------------------------------------------------------------
// Kernel A: zero the bucket counts (must run every launch; graph-replayable)
// ---------------------------------------------------------------------------
__global__ void zero_counts_kernel() {
    int i = blockIdx.x * blockDim.x + threadIdx.x;
    if (i < BB * RR) g_count[i] = 0;
}

// ---------------------------------------------------------------------------
// Kernel B: counting-bucketize items by (batch, role)
// ---------------------------------------------------------------------------
__global__ void build_buckets_kernel(const int* __restrict__ batch_idx,
                                     const int* __restrict__ slot_idx,
                                     const int* __restrict__ role_idx) {
    int item = blockIdx.x * blockDim.x + threadIdx.x;
    if (item >= NITEMS) return;
    int b    = batch_idx[item];
    int rho  = role_idx[item];
    int slot = slot_idx[item];
    int bkt  = b * RR + rho;
    int pos  = atomicAdd(&g_count[bkt], 1);
    if (pos < CAP) g_bucket[bkt * CAP + pos] = (slot << 18) | item;
}

// ---------------------------------------------------------------------------
// Kernel C: gather. One warp owns output rows (2k, 2k+1) of batch b.
//   row 2k   <- car(role 4k, od0*w0) + cdr(role 4k+1, od1*w1, skip k==0)
//               + cons(role k, od2*w2)                      [car/cdr only k<1024]
//   row 2k+1 <- car(role 4k+2) + cdr(role 4k+3)
//               + cons(role k, od2*w3) + (k==0: od2*root)
// ---------------------------------------------------------------------------
__device__ __forceinline__ void bucket_accum1(
    int bkt, int cnt, const float* __restrict__ awb,
    const float* __restrict__ mem, int lane,
    float coef, int wcomp, float4& acc)
{
    cnt = min(cnt, CAP);
    int entry = (lane < cnt) ? g_bucket[bkt * CAP + lane] : 0;
    for (int i = 0; i < cnt; i++) {
        int e = __shfl_sync(0xffffffffu, entry, i);
        int item = e & 0x3FFFF;
        int slot = e >> 18;
        float wv = awb[slot * 4 + wcomp];                    // broadcast 4B
        float4 m = ((const float4*)(mem + (size_t)item * FF))[lane];
        float c = coef * wv;
        acc.x += c * m.x; acc.y += c * m.y; acc.z += c * m.z; acc.w += c * m.w;
    }
}

__global__ void __launch_bounds__(256) gather_kernel(
    const float* __restrict__ mem,       // (N, F)
    const float* __restrict__ arg_w,     // (B, L, 4)
    const float* __restrict__ root,      // (B, F)
    const float* __restrict__ op_dist,   // (B, 3)
    float* __restrict__ out)             // (B, R, F)
{
    int pair = blockIdx.x * (blockDim.x >> 5) + (threadIdx.x >> 5);
    if (pair >= NPAIRS) return;
    const int lane = threadIdx.x & 31;
    const int b = pair >> 11;            // pair / 2048
    const int k = pair & 2047;

    const float od0 = op_dist[b * 3 + 0];
    const float od1 = op_dist[b * 3 + 1];
    const float od2 = op_dist[b * 3 + 2];
    const float* awb = arg_w + (size_t)b * LL * 4;
    const int cbase = b * RR;

    float4 a0 = make_float4(0.f, 0.f, 0.f, 0.f);
    float4 a1 = make_float4(0.f, 0.f, 0.f, 0.f);

    // cons: bucket role k feeds BOTH rows (read each item once)
    {
        int bkt = cbase + k;
        int cnt = min(g_count[bkt], CAP);
        int entry = (lane < cnt) ? g_bucket[bkt * CAP + lane] : 0;
        for (int i = 0; i < cnt; i++) {
            int e = __shfl_sync(0xffffffffu, entry, i);
            int item = e & 0x3FFFF;
            int slot = e >> 18;
            float4 w = *(const float4*)(awb + slot * 4);
            float4 m = ((const float4*)(mem + (size_t)item * FF))[lane];
            float c0 = od2 * w.z;
            float c1 = od2 * w.w;
            a0.x += c0 * m.x; a0.y += c0 * m.y; a0.z += c0 * m.z; a0.w += c0 * m.w;
            a1.x += c1 * m.x; a1.y += c1 * m.y; a1.z += c1 * m.z; a1.w += c1 * m.w;
        }
    }

    if (k < 1024) {
        int rbase = cbase + 4 * k;
        int4 cnt4 = *(const int4*)&g_count[rbase];            // 4 contiguous counts
        bucket_accum1(rbase + 0, cnt4.x, awb, mem, lane, od0, 0, a0);   // car  row 2k
        if (k != 0)
            bucket_accum1(rbase + 1, cnt4.y, awb, mem, lane, od1, 1, a0); // cdr row 2k
        bucket_accum1(rbase + 2, cnt4.z, awb, mem, lane, od0, 0, a1);   // car  row 2k+1
        bucket_accum1(rbase + 3, cnt4.w, awb, mem, lane, od1, 1, a1);   // cdr  row 2k+1
    }

    if (k == 0) {
        // row 1 += od2 * root_filler[b]
        float4 rf = ((const float4*)(root + (size_t)b * FF))[lane];
        a1.x += od2 * rf.x; a1.y += od2 * rf.y; a1.z += od2 * rf.z; a1.w += od2 * rf.w;
    }

    float* obase = out + ((size_t)b * RR + 2 * (size_t)k) * FF;
    ((float4*)obase)[lane]      = a0;                        // row 2k
    ((float4*)(obase + FF))[lane] = a1;                      // row 2k+1
}

// ---------------------------------------------------------------------------
extern "C" void kernel_launch(void* const* d_in, const int* in_sizes, int n_in,
                              void* d_out, int out_size) {
    const float* mem     = (const float*)d_in[0];  // (N, F)
    const float* arg_w   = (const float*)d_in[1];  // (B, L, 4)
    const float* root    = (const float*)d_in[2];  // (B, F)
    const float* op_dist = (const float*)d_in[3];  // (B, 3)
    const int*   batch_i = (const int*)d_in[4];
    const int*   slot_i  = (const int*)d_in[5];
    const int*   role_i  = (const int*)d_in[6];
    float* out = (float*)d_out;

    zero_counts_kernel<<<(BB * RR + 255) / 256, 256>>>();
    build_buckets_kernel<<<(NITEMS + 255) / 256, 256>>>(batch_i, slot_i, role_i);

    const int warps_per_block = 8;                 // 256 threads
    const int blocks = NPAIRS / warps_per_block;   // 8192
    gather_kernel<<<blocks, 256>>>(mem, arg_w, root, op_dist, out);
}

// round 4
// speedup vs baseline: 1.2939x; 1.2939x over previous
#include <cuda_runtime.h>
#include <cstdint>

#define BB 32
#define LL 128
#define FF 128
#define RR 4096
#define NITEMS 262144
#define CAP 32

// Scratch (device globals; no allocation allowed)
__device__ int g_count[BB * RR];           // 512 KB  (memset to 0 each launch)
__device__ int g_bucket[BB * RR * CAP];    // 16 MB, entry = (slot<<18)|item

// ---------------------------------------------------------------------------
// Bucketize items by (batch, role).
// ---------------------------------------------------------------------------
__global__ void build_buckets_kernel(const int* __restrict__ batch_idx,
                                     const int* __restrict__ slot_idx,
                                     const int* __restrict__ role_idx) {
    int item = blockIdx.x * blockDim.x + threadIdx.x;
    if (item >= NITEMS) return;
    int b    = batch_idx[item];
    int rho  = role_idx[item];
    int slot = slot_idx[item];
    int bkt  = b * RR + rho;
    int pos  = atomicAdd(&g_count[bkt], 1);
    if (pos < CAP) g_bucket[bkt * CAP + pos] = (slot << 18) | item;
}

// ---------------------------------------------------------------------------
// Gather. Each warp owns TWO row pairs of batch b:
//   heavy pair k  (k in [0,1024)):   rows 2k, 2k+1
//       row 2k   <- car(bucket 4k,  od0*w0) + cdr(bucket 4k+1, od1*w1, skip k==0)
//                   + cons(bucket k, od2*w2)
//       row 2k+1 <- car(bucket 4k+2) + cdr(bucket 4k+3)
//                   + cons(bucket k, od2*w3) + (k==0: od2*root)
//   light pair k+1024:               rows 2k+2048, 2k+2049  (cons bucket k+1024 only)
// Lane l holds float4 chunk l of each 128-float row.
// ---------------------------------------------------------------------------

// accumulate a bucket feeding ONE accumulator with weight component selected
// by caller: w_val = awb[slot*4 + wcomp], coefficient coef.
__device__ __forceinline__ void accum_one(
    const float* __restrict__ mem, const float* __restrict__ awb,
    int entry, int cnt, int lane, float coef, int wcomp, float4& acc)
{
    int i = 0;
    for (; i + 1 < cnt; i += 2) {
        int e0 = __shfl_sync(0xffffffffu, entry, i);
        int e1 = __shfl_sync(0xffffffffu, entry, i + 1);
        float w0 = awb[((e0 >> 18) << 2) + wcomp];
        float w1 = awb[((e1 >> 18) << 2) + wcomp];
        float4 m0 = ((const float4*)(mem + (size_t)(e0 & 0x3FFFF) * FF))[lane];
        float4 m1 = ((const float4*)(mem + (size_t)(e1 & 0x3FFFF) * FF))[lane];
        float c0 = coef * w0, c1 = coef * w1;
        acc.x += c0 * m0.x; acc.y += c0 * m0.y; acc.z += c0 * m0.z; acc.w += c0 * m0.w;
        acc.x += c1 * m1.x; acc.y += c1 * m1.y; acc.z += c1 * m1.z; acc.w += c1 * m1.w;
    }
    if (i < cnt) {
        int e0 = __shfl_sync(0xffffffffu, entry, i);
        float w0 = awb[((e0 >> 18) << 2) + wcomp];
        float4 m0 = ((const float4*)(mem + (size_t)(e0 & 0x3FFFF) * FF))[lane];
        float c0 = coef * w0;
        acc.x += c0 * m0.x; acc.y += c0 * m0.y; acc.z += c0 * m0.z; acc.w += c0 * m0.w;
    }
}

// accumulate a cons bucket feeding TWO accumulators (w2 -> even row, w3 -> odd).
__device__ __forceinline__ void accum_cons(
    const float* __restrict__ mem, const float* __restrict__ awb,
    int entry, int cnt, int lane, float od2, float4& ae, float4& ao)
{
    int i = 0;
    for (; i + 1 < cnt; i += 2) {
        int e0 = __shfl_sync(0xffffffffu, entry, i);
        int e1 = __shfl_sync(0xffffffffu, entry, i + 1);
        float4 w40 = *(const float4*)(awb + ((e0 >> 18) << 2));
        float4 w41 = *(const float4*)(awb + ((e1 >> 18) << 2));
        float4 m0 = ((const float4*)(mem + (size_t)(e0 & 0x3FFFF) * FF))[lane];
        float4 m1 = ((const float4*)(mem + (size_t)(e1 & 0x3FFFF) * FF))[lane];
        float ce0 = od2 * w40.z, co0 = od2 * w40.w;
        float ce1 = od2 * w41.z, co1 = od2 * w41.w;
        ae.x += ce0 * m0.x; ae.y += ce0 * m0.y; ae.z += ce0 * m0.z; ae.w += ce0 * m0.w;
        ao.x += co0 * m0.x; ao.y += co0 * m0.y; ao.z += co0 * m0.z; ao.w += co0 * m0.w;
        ae.x += ce1 * m1.x; ae.y += ce1 * m1.y; ae.z += ce1 * m1.z; ae.w += ce1 * m1.w;
        ao.x += co1 * m1.x; ao.y += co1 * m1.y; ao.z += co1 * m1.z; ao.w += co1 * m1.w;
    }
    if (i < cnt) {
        int e0 = __shfl_sync(0xffffffffu, entry, i);
        float4 w40 = *(const float4*)(awb + ((e0 >> 18) << 2));
        float4 m0 = ((const float4*)(mem + (size_t)(e0 & 0x3FFFF) * FF))[lane];
        float ce0 = od2 * w40.z, co0 = od2 * w40.w;
        ae.x += ce0 * m0.x; ae.y += ce0 * m0.y; ae.z += ce0 * m0.z; ae.w += ce0 * m0.w;
        ao.x += co0 * m0.x; ao.y += co0 * m0.y; ao.z += co0 * m0.z; ao.w += co0 * m0.w;
    }
}

__global__ void __launch_bounds__(256) gather_kernel(
    const float* __restrict__ mem,       // (N, F)
    const float* __restrict__ arg_w,     // (B, L, 4)
    const float* __restrict__ root,      // (B, F)
    const float* __restrict__ op_dist,   // (B, 3)
    float* __restrict__ out)             // (B, R, F)
{
    int w = blockIdx.x * (blockDim.x >> 5) + (threadIdx.x >> 5);  // [0, 32768)
    if (w >= BB * 1024) return;
    const int lane = threadIdx.x & 31;
    const int b = w >> 10;
    const int k = w & 1023;
    const int base = b * RR;

    const float od0 = op_dist[b * 3 + 0];
    const float od1 = op_dist[b * 3 + 1];
    const float od2 = op_dist[b * 3 + 2];
    const float* awb = arg_w + (size_t)b * LL * 4;

    // ---- counts for all 6 buckets (issued together) ----
    int4 c4 = *(const int4*)&g_count[base + 4 * k];    // car/cdr buckets 4k..4k+3
    int cch = g_count[base + k];                       // heavy cons bucket
    int ccl = g_count[base + k + 1024];                // light cons bucket
    int c0 = min(c4.x, CAP), c1 = min(c4.y, CAP);
    int c2 = min(c4.z, CAP), c3 = min(c4.w, CAP);
    cch = min(cch, CAP); ccl = min(ccl, CAP);

    // ---- preload entries for all 6 buckets (6 independent LDGs) ----
    int e_ch = (lane < cch) ? g_bucket[(base + k) * CAP + lane] : 0;
    int e_cl = (lane < ccl) ? g_bucket[(base + k + 1024) * CAP + lane] : 0;
    int e0 = (lane < c0) ? g_bucket[(base + 4 * k + 0) * CAP + lane] : 0;
    int e1 = (lane < c1) ? g_bucket[(base + 4 * k + 1) * CAP + lane] : 0;
    int e2 = (lane < c2) ? g_bucket[(base + 4 * k + 2) * CAP + lane] : 0;
    int e3 = (lane < c3) ? g_bucket[(base + 4 * k + 3) * CAP + lane] : 0;

    float4 a0 = make_float4(0.f, 0.f, 0.f, 0.f);   // heavy row 2k
    float4 a1 = make_float4(0.f, 0.f, 0.f, 0.f);   // heavy row 2k+1
    float4 b0 = make_float4(0.f, 0.f, 0.f, 0.f);   // light row 2k+2048
    float4 b1 = make_float4(0.f, 0.f, 0.f, 0.f);   // light row 2k+2049

    accum_cons(mem, awb, e_ch, cch, lane, od2, a0, a1);
    accum_cons(mem, awb, e_cl, ccl, lane, od2, b0, b1);
    accum_one(mem, awb, e0, c0, lane, od0, 0, a0);                 // car  row 2k
    if (k != 0)
        accum_one(mem, awb, e1, c1, lane, od1, 1, a0);             // cdr  row 2k
    accum_one(mem, awb, e2, c2, lane, od0, 0, a1);                 // car  row 2k+1
    accum_one(mem, awb, e3, c3, lane, od1, 1, a1);                 // cdr  row 2k+1

    if (k == 0) {   // row 1 += od2 * root_filler[b]
        float4 rf = ((const float4*)(root + (size_t)b * FF))[lane];
        a1.x += od2 * rf.x; a1.y += od2 * rf.y; a1.z += od2 * rf.z; a1.w += od2 * rf.w;
    }

    float* oh = out + ((size_t)base + 2 * (size_t)k) * FF;
    ((float4*)oh)[lane]        = a0;
    ((float4*)(oh + FF))[lane] = a1;
    float* ol = oh + (size_t)2048 * FF;
    ((float4*)ol)[lane]        = b0;
    ((float4*)(ol + FF))[lane] = b1;
}

// ---------------------------------------------------------------------------
extern "C" void kernel_launch(void* const* d_in, const int* in_sizes, int n_in,
                              void* d_out, int out_size) {
    const float* mem     = (const float*)d_in[0];
    const float* arg_w   = (const float*)d_in[1];
    const float* root    = (const float*)d_in[2];
    const float* op_dist = (const float*)d_in[3];
    const int*   batch_i = (const int*)d_in[4];
    const int*   slot_i  = (const int*)d_in[5];
    const int*   role_i  = (const int*)d_in[6];
    float* out = (float*)d_out;

    // Zero bucket counts via a memset node (graph-capturable, ~1us).
    void* cnt_ptr = nullptr;
    cudaGetSymbolAddress(&cnt_ptr, g_count);
    cudaMemsetAsync(cnt_ptr, 0, sizeof(int) * BB * RR, 0);

    build_buckets_kernel<<<(NITEMS + 255) / 256, 256>>>(batch_i, slot_i, role_i);

    const int nwarps = BB * 1024;                  // 32768
    const int wpb = 8;                             // 256 threads
    gather_kernel<<<nwarps / wpb, 256>>>(mem, arg_w, root, op_dist, out);
}